// round 7
// baseline (speedup 1.0000x reference)
#include <cuda_runtime.h>

#define BATCH   128
#define NANCH   8732
#define NCLS    21
#define NLOG    25
#define MAXOUT  5
#define CONF    0.5f
#define DEC_T   128
#define CSTRIDE 32                         // counter pad: 32 ints = 128 B

// Device globals (zero-init at load; g_cnt restored to zero by nms_kernel
// every launch -> graph-replay consistent, no reset kernel).
__device__ int                 g_cnt[BATCH * CSTRIDE];
__device__ float4              g_cbox[BATCH * NANCH];
__device__ unsigned long long  g_ckey[BATCH * NANCH];
__device__ float               g_ccls[BATCH * NANCH];

// ---------------------------------------------------------------------------
// Decode + softmax-max/argmax + candidate compaction (R3 configuration:
// 128-thread blocks, 12.8 KB smem tile, high occupancy, front-batched LDG).
// ---------------------------------------------------------------------------
__global__ void __launch_bounds__(DEC_T)
decode_kernel(const float* __restrict__ logits, const float* __restrict__ db) {
    __shared__ float tile[DEC_T * NLOG];
    const int NV = DEC_T * NLOG / 4;                       // 800 float4

    long long base = (long long)blockIdx.x * DEC_T;
    const float4* __restrict__ src = (const float4*)(logits + base * NLOG);
    float4* dst = (float4*)tile;

    float4 v[7];
    int tid = threadIdx.x;
#pragma unroll
    for (int k = 0; k < 7; k++) {
        int i = tid + k * DEC_T;
        if (i < NV) v[k] = src[i];
    }
#pragma unroll
    for (int k = 0; k < 7; k++) {
        int i = tid + k * DEC_T;
        if (i < NV) dst[i] = v[k];
    }
    __syncthreads();

    int gid = (int)base + tid;
    const float* L = tile + tid * NLOG;

    float best = L[4];
    int   bi   = 0;
#pragma unroll
    for (int c = 1; c < NCLS; c++) {
        float vv = L[4 + c];
        if (vv > best) { best = vv; bi = c; }
    }
    float sum = 0.f;
#pragma unroll
    for (int c = 0; c < NCLS; c++) sum += __expf(L[4 + c] - best);
    float score = 1.0f / sum;

    if (bi != 0 && score > CONF) {
        int b = gid / NANCH;
        int n = gid % NANCH;
        float4 d = ((const float4*)db)[n];                 // y0,x0,y1,x1
        float cy = 0.5f * (d.z + d.x);
        float cx = 0.5f * (d.w + d.y);
        float h  = d.z - d.x;
        float w  = d.w - d.y;
        float ncy = L[0] * h + cy;
        float ncx = L[1] * w + cx;
        float nh  = __expf(L[2]) * h;
        float nw  = __expf(L[3]) * w;
        float4 box;
        box.x = fminf(fmaxf(ncy - 0.5f * nh, 0.f), 1.f);
        box.y = fminf(fmaxf(ncx - 0.5f * nw, 0.f), 1.f);
        box.z = fminf(fmaxf(ncy + 0.5f * nh, 0.f), 1.f);
        box.w = fminf(fmaxf(ncx + 0.5f * nw, 0.f), 1.f);

        int slot = atomicAdd(&g_cnt[b * CSTRIDE], 1);
        size_t o = (size_t)b * NANCH + slot;
        // key: [score bits|0x80000000][NANCH-n : 14b][slot : 14b]
        unsigned hi = __float_as_uint(score) | 0x80000000u;
        unsigned lo = ((unsigned)(NANCH - n) << 14) | (unsigned)slot;
        g_ckey[o] = ((unsigned long long)hi << 32) | lo;
        g_cbox[o] = box;
        g_ccls[o] = (float)bi;
    }
}

// ---------------------------------------------------------------------------
// NMS: one warp per batch. No smem, no block barriers — warp-serial fused
// suppress+argmax straight from L2/L1 (M is small; L1-resident after first
// touch). Also resets g_cnt[b] for the next graph replay.
// ---------------------------------------------------------------------------
__global__ void __launch_bounds__(32)
nms_kernel(float* __restrict__ out) {
    int b   = blockIdx.x;
    int tid = threadIdx.x;

    int M = g_cnt[b * CSTRIDE];            // warp-broadcast load
    __syncwarp();
    if (tid == 0) g_cnt[b * CSTRIDE] = 0;  // reset for next replay

    size_t base = (size_t)b * NANCH;
    unsigned long long* keys  = g_ckey + base;
    const float4*       boxes = g_cbox + base;
    const float*        cls   = g_ccls + base;

    // initial warp argmax
    unsigned long long bp = 0ull;
    for (int i = tid; i < M; i += 32) {
        unsigned long long k = keys[i];
        if (k > bp) bp = k;
    }
#pragma unroll
    for (int off = 16; off > 0; off >>= 1) {
        unsigned long long o = __shfl_xor_sync(0xffffffffu, bp, off);
        if (o > bp) bp = o;
    }

    float* ob = out + (size_t)b * MAXOUT * 6;
    for (int t = 0; t < MAXOUT; t++) {
        if (bp == 0ull) {
            if (tid == 0) {
                for (int tt = t; tt < MAXOUT; tt++) {
                    float* o = ob + tt * 6;
                    o[0] = o[1] = o[2] = o[3] = o[4] = o[5] = 0.f;
                }
            }
            return;
        }
        int   pos = (int)(bp & 0x3FFFull);
        float sc  = __uint_as_float((unsigned)(bp >> 32) & 0x7FFFFFFFu);
        float4 B  = boxes[pos];
        if (tid == 0) {
            float* o = ob + t * 6;
            o[0] = B.x; o[1] = B.y; o[2] = B.z; o[3] = B.w;
            o[4] = cls[pos]; o[5] = sc;
        }
        if (t == MAXOUT - 1) return;

        // fused suppression + next argmax (each lane owns its stripe)
        float a1 = (B.z - B.x) * (B.w - B.y);
        bp = 0ull;
        for (int i = tid; i < M; i += 32) {
            unsigned long long k = keys[i];
            if (!k) continue;
            float4 C = boxes[i];
            float ty  = fmaxf(B.x, C.x);
            float tx  = fmaxf(B.y, C.y);
            float by  = fminf(B.z, C.z);
            float bxr = fminf(B.w, C.w);
            float hh  = fmaxf(by - ty, 0.f);
            float ww  = fmaxf(bxr - tx, 0.f);
            float inter = hh * ww;
            float a2 = (C.z - C.x) * (C.w - C.y);
            float iou = inter / (a1 + a2 - inter + 1e-12f);
            if (iou > 0.5f) keys[i] = 0ull;
            else if (k > bp) bp = k;
        }
#pragma unroll
        for (int off = 16; off > 0; off >>= 1) {
            unsigned long long o = __shfl_xor_sync(0xffffffffu, bp, off);
            if (o > bp) bp = o;
        }
    }
}

// ---------------------------------------------------------------------------
extern "C" void kernel_launch(void* const* d_in, const int* in_sizes, int n_in,
                              void* d_out, int out_size) {
    const float* logits = (const float*)d_in[0];   // [128, 8732, 25]
    const float* db     = (const float*)d_in[1];   // [8732, 4]
    float*       out    = (float*)d_out;           // [128, 5, 6]

    decode_kernel<<<BATCH * NANCH / DEC_T, DEC_T>>>(logits, db);
    nms_kernel<<<BATCH, 32>>>(out);
}

// round 8
// speedup vs baseline: 1.1712x; 1.1712x over previous
#include <cuda_runtime.h>

#define BATCH   128
#define NANCH   8732
#define NCLS    21
#define NLOG    25
#define MAXOUT  5
#define CONF    0.5f
#define DEC_T   128
#define NBLK    8732                       // (BATCH*NANCH)/DEC_T
#define CSTRIDE 32                         // counter pad: 128 B
#define SCAP    448                        // smem-staged candidate cap
#define RCAP    2048                       // register-bitmask cap (64 * 32)

__device__ int                 g_cnt[BATCH * CSTRIDE];
__device__ int                 g_done[BATCH * CSTRIDE];
__device__ float4              g_cbox[BATCH * NANCH];
__device__ unsigned long long  g_ckey[BATCH * NANCH];
__device__ float               g_ccls[BATCH * NANCH];

// ---------------------------------------------------------------------------
// NMS for one batch, run by the last-arriving block of that batch.
// Loop body has NO stores: survivors tracked in a per-lane register bitmask,
// so candidate loads pipeline instead of serializing behind aliasing.
// ---------------------------------------------------------------------------
__device__ __forceinline__ void do_nms(int b, char* sh, float* __restrict__ out,
                                       int tid) {
    __threadfence();                                   // acquire
    int M = g_cnt[b * CSTRIDE];
    size_t base = (size_t)b * NANCH;

    unsigned long long* skey = (unsigned long long*)sh;
    float4*             sbox = (float4*)(sh + SCAP * 8);

    bool fits = (M <= SCAP);
    if (fits) {
        for (int i = tid; i < M; i += DEC_T) {
            skey[i] = g_ckey[base + i];
            sbox[i] = g_cbox[base + i];
        }
    }
    __syncthreads();

    if (tid < 32) {
        const unsigned long long* __restrict__ keys =
            fits ? skey : (g_ckey + base);
        const float4* __restrict__ boxes = fits ? sbox : (g_cbox + base);
        float* ob = out + (size_t)b * MAXOUT * 6;

        if (M <= RCAP) {
            unsigned long long alive = ~0ull;          // bit k = elem tid+32k
            unsigned long long bp = 0ull;
            for (int i = tid; i < M; i += 32) {
                unsigned long long k = keys[i];
                if (k > bp) bp = k;
            }
#pragma unroll
            for (int off = 16; off > 0; off >>= 1) {
                unsigned long long o = __shfl_xor_sync(0xffffffffu, bp, off);
                if (o > bp) bp = o;
            }
            for (int t = 0; t < MAXOUT; t++) {
                if (bp == 0ull) {
                    if (tid == 0)
                        for (int tt = t; tt < MAXOUT; tt++) {
                            float* o = ob + tt * 6;
                            o[0]=o[1]=o[2]=o[3]=o[4]=o[5]=0.f;
                        }
                    break;
                }
                int   pos = (int)(bp & 0x3FFFull);
                float sc  = __uint_as_float((unsigned)(bp >> 32) & 0x7FFFFFFFu);
                float4 B  = boxes[pos];
                if (tid == 0) {
                    float* o = ob + t * 6;
                    o[0]=B.x; o[1]=B.y; o[2]=B.z; o[3]=B.w;
                    o[4]=g_ccls[base + pos]; o[5]=sc;
                }
                if (t == MAXOUT - 1) break;

                float a1 = (B.z - B.x) * (B.w - B.y);
                bp = 0ull;
                int kk = 0;
                for (int i = tid; i < M; i += 32, kk++) {
                    if (!((alive >> kk) & 1ull)) continue;
                    float4 C = boxes[i];
                    float ty  = fmaxf(B.x, C.x);
                    float tx  = fmaxf(B.y, C.y);
                    float by  = fminf(B.z, C.z);
                    float bxr = fminf(B.w, C.w);
                    float hh  = fmaxf(by - ty, 0.f);
                    float ww  = fmaxf(bxr - tx, 0.f);
                    float inter = hh * ww;
                    float a2 = (C.z - C.x) * (C.w - C.y);
                    float iou = inter / (a1 + a2 - inter + 1e-12f);
                    if (iou > 0.5f) alive &= ~(1ull << kk);
                    else {
                        unsigned long long k = keys[i];
                        if (k > bp) bp = k;
                    }
                }
#pragma unroll
                for (int off = 16; off > 0; off >>= 1) {
                    unsigned long long o = __shfl_xor_sync(0xffffffffu, bp, off);
                    if (o > bp) bp = o;
                }
            }
        } else {
            // destructive fallback (M > RCAP; never expected)
            unsigned long long* kg = g_ckey + base;
            unsigned long long bp = 0ull;
            for (int i = tid; i < M; i += 32) {
                unsigned long long k = kg[i];
                if (k > bp) bp = k;
            }
#pragma unroll
            for (int off = 16; off > 0; off >>= 1) {
                unsigned long long o = __shfl_xor_sync(0xffffffffu, bp, off);
                if (o > bp) bp = o;
            }
            for (int t = 0; t < MAXOUT; t++) {
                if (bp == 0ull) {
                    if (tid == 0)
                        for (int tt = t; tt < MAXOUT; tt++) {
                            float* o = ob + tt * 6;
                            o[0]=o[1]=o[2]=o[3]=o[4]=o[5]=0.f;
                        }
                    break;
                }
                int   pos = (int)(bp & 0x3FFFull);
                float sc  = __uint_as_float((unsigned)(bp >> 32) & 0x7FFFFFFFu);
                float4 B  = boxes[pos];
                if (tid == 0) {
                    float* o = ob + t * 6;
                    o[0]=B.x; o[1]=B.y; o[2]=B.z; o[3]=B.w;
                    o[4]=g_ccls[base + pos]; o[5]=sc;
                }
                if (t == MAXOUT - 1) break;
                float a1 = (B.z - B.x) * (B.w - B.y);
                bp = 0ull;
                for (int i = tid; i < M; i += 32) {
                    unsigned long long k = kg[i];
                    if (!k) continue;
                    float4 C = boxes[i];
                    float ty  = fmaxf(B.x, C.x);
                    float tx  = fmaxf(B.y, C.y);
                    float by  = fminf(B.z, C.z);
                    float bxr = fminf(B.w, C.w);
                    float hh  = fmaxf(by - ty, 0.f);
                    float ww  = fmaxf(bxr - tx, 0.f);
                    float inter = hh * ww;
                    float a2 = (C.z - C.x) * (C.w - C.y);
                    float iou = inter / (a1 + a2 - inter + 1e-12f);
                    if (iou > 0.5f) kg[i] = 0ull;
                    else if (k > bp) bp = k;
                }
#pragma unroll
                for (int off = 16; off > 0; off >>= 1) {
                    unsigned long long o = __shfl_xor_sync(0xffffffffu, bp, off);
                    if (o > bp) bp = o;
                }
            }
        }
    }
    __syncthreads();
    if (tid == 0) {                                    // reset for next replay
        g_cnt[b * CSTRIDE]  = 0;
        g_done[b * CSTRIDE] = 0;
    }
}

// ---------------------------------------------------------------------------
// Fused: decode (R3-proven shape) + last-block-per-batch NMS.
// grid = 8732 blocks x 128 threads, one anchor per thread (flattened B*N).
// ---------------------------------------------------------------------------
__global__ void __launch_bounds__(DEC_T, 12)
fused_kernel(const float* __restrict__ logits, const float* __restrict__ db,
             float* __restrict__ out) {
    __shared__ __align__(16) char sh[DEC_T * NLOG * 4];   // 12.8 KB, reused
    __shared__ int s_run0, s_run1;

    float* tile = (float*)sh;
    const int NV = DEC_T * NLOG / 4;                   // 800 float4

    int bid = blockIdx.x;
    int tid = threadIdx.x;
    long long base = (long long)bid * DEC_T;

    const float4* __restrict__ src = (const float4*)(logits + base * NLOG);
    float4* dst = (float4*)tile;

    float4 v[7];
#pragma unroll
    for (int k = 0; k < 7; k++) {
        int i = tid + k * DEC_T;
        if (i < NV) v[k] = src[i];
    }
#pragma unroll
    for (int k = 0; k < 7; k++) {
        int i = tid + k * DEC_T;
        if (i < NV) dst[i] = v[k];
    }
    __syncthreads();

    int gid = (int)base + tid;
    {
        const float* L = tile + tid * NLOG;
        float best = L[4];
        int   bi   = 0;
#pragma unroll
        for (int c = 1; c < NCLS; c++) {
            float vv = L[4 + c];
            if (vv > best) { best = vv; bi = c; }
        }
        float sum = 0.f;
#pragma unroll
        for (int c = 0; c < NCLS; c++) sum += __expf(L[4 + c] - best);
        float score = 1.0f / sum;

        if (bi != 0 && score > CONF) {
            int b = gid / NANCH;
            int n = gid % NANCH;
            float4 d = ((const float4*)db)[n];
            float cy = 0.5f * (d.z + d.x);
            float cx = 0.5f * (d.w + d.y);
            float h  = d.z - d.x;
            float w  = d.w - d.y;
            float ncy = L[0] * h + cy;
            float ncx = L[1] * w + cx;
            float nh  = __expf(L[2]) * h;
            float nw  = __expf(L[3]) * w;
            float4 box;
            box.x = fminf(fmaxf(ncy - 0.5f * nh, 0.f), 1.f);
            box.y = fminf(fmaxf(ncx - 0.5f * nw, 0.f), 1.f);
            box.z = fminf(fmaxf(ncy + 0.5f * nh, 0.f), 1.f);
            box.w = fminf(fmaxf(ncx + 0.5f * nw, 0.f), 1.f);

            int slot = atomicAdd(&g_cnt[b * CSTRIDE], 1);
            size_t o = (size_t)b * NANCH + slot;
            unsigned hi = __float_as_uint(score) | 0x80000000u;
            unsigned lo = ((unsigned)(NANCH - n) << 14) | (unsigned)slot;
            g_ckey[o] = ((unsigned long long)hi << 32) | lo;
            g_cbox[o] = box;
            g_ccls[o] = (float)bi;
        }
    }

    // ---- publish & last-block election (block may straddle 2 batches) ----
    __syncthreads();                       // writes visible block-wide; smem free
    int b0 = (int)(base / NANCH);
    int b1 = (int)((base + DEC_T - 1) / NANCH);
    if (tid == 0) {
        __threadfence();
        int p = atomicAdd(&g_done[b0 * CSTRIDE], 1);
        int e = ((b0 + 1) * NANCH - 1) / DEC_T - (b0 * NANCH) / DEC_T + 1;
        s_run0 = (p == e - 1);
        s_run1 = 0;
        if (b1 != b0) {
            p = atomicAdd(&g_done[b1 * CSTRIDE], 1);
            e = ((b1 + 1) * NANCH - 1) / DEC_T - (b1 * NANCH) / DEC_T + 1;
            s_run1 = (p == e - 1);
        }
    }
    __syncthreads();
    if (!s_run0 && !s_run1) return;

    if (s_run0) do_nms(b0, sh, out, tid);
    if (s_run1) {
        __syncthreads();
        do_nms(b1, sh, out, tid);
    }
}

// ---------------------------------------------------------------------------
extern "C" void kernel_launch(void* const* d_in, const int* in_sizes, int n_in,
                              void* d_out, int out_size) {
    const float* logits = (const float*)d_in[0];   // [128, 8732, 25]
    const float* db     = (const float*)d_in[1];   // [8732, 4]
    float*       out    = (float*)d_out;           // [128, 5, 6]

    fused_kernel<<<NBLK, DEC_T>>>(logits, db, out);
}